// round 1
// baseline (speedup 1.0000x reference)
#include <cuda_runtime.h>
#include <cstddef>

#define HH 51     // hidden size
#define GG 204    // 4*H real gates
#define GP 224    // padded gate slots (56 groups of 4)
#define BT 16     // batch rows per block
#define NT 224    // threads per block (56 gate-groups x 4 batch-groups)
#define TT 512    // timesteps
#define BB 2048   // batch
#define TCH 64    // x staging chunk (timesteps)

#define SMEM_FLOATS (3*HH*GP + 3*GP + 64 + 2*HH*BT + GP*BT + BT*TCH)

__device__ __forceinline__ float sigm(float v) { return 1.f / (1.f + __expf(-v)); }

__global__ void __launch_bounds__(NT, 1) lstm2_persistent_kernel(
    const float* __restrict__ x,
    const float* __restrict__ Wih1, const float* __restrict__ bih1,
    const float* __restrict__ Whh1, const float* __restrict__ bhh1,
    const float* __restrict__ Wih2, const float* __restrict__ bih2,
    const float* __restrict__ Whh2, const float* __restrict__ bhh2,
    const float* __restrict__ fcwg, const float* __restrict__ fcbg,
    float* __restrict__ out)
{
    extern __shared__ float sm[];
    float* sWh1 = sm;                 // [HH][GP] transposed: sWh1[k*GP+g] = W_hh1[g][k]
    float* sWi2 = sWh1 + HH*GP;       // [HH][GP]
    float* sWh2 = sWi2 + HH*GP;       // [HH][GP]
    float* sb1  = sWh2 + HH*GP;       // [GP] combined bias cell1
    float* sb2  = sb1 + GP;           // [GP] combined bias cell2
    float* swi1 = sb2 + GP;           // [GP] W_ih1 column
    float* sfcw = swi1 + GP;          // [64]
    float* h1s  = sfcw + 64;          // [HH][BT]
    float* h2s  = h1s + HH*BT;        // [HH][BT]
    float* ag   = h2s + HH*BT;        // [GP][BT] activated gates scratch
    float* xs   = ag + GP*BT;         // [BT][TCH] x staging

    const int tid = threadIdx.x;
    const int b0  = blockIdx.x * BT;

    // ---- one-time weight prep (transpose into SMEM, pad slots >= 204 with 0) ----
    for (int i = tid; i < HH*GP; i += NT) {
        int k = i / GP, g = i % GP;
        bool real = (g < GG);
        sWh1[i] = real ? Whh1[g*HH + k] : 0.f;
        sWi2[i] = real ? Wih2[g*HH + k] : 0.f;
        sWh2[i] = real ? Whh2[g*HH + k] : 0.f;
    }
    for (int g = tid; g < GP; g += NT) {
        bool real = (g < GG);
        sb1[g]  = real ? (bih1[g] + bhh1[g]) : 0.f;
        sb2[g]  = real ? (bih2[g] + bhh2[g]) : 0.f;
        swi1[g] = real ? Wih1[g] : 0.f;      // W_ih1 is [4H,1]
    }
    for (int k = tid; k < 64; k += NT) sfcw[k] = (k < HH) ? fcwg[k] : 0.f;
    for (int i = tid; i < HH*BT; i += NT) { h1s[i] = 0.f; h2s[i] = 0.f; }
    const float fcb = fcbg[0];

    // thread mapping: 56 gate-groups (4 gates each) x 4 batch-groups (4 each)
    const int gg_ = tid % 56;
    const int bq  = tid / 56;
    const int gbase = gg_ * 4;
    const int bbase = bq * 4;

    __syncthreads();

    float bs1r[4], bs2r[4], wi1r[4];
    bool isth[4];
#pragma unroll
    for (int gi = 0; gi < 4; ++gi) {
        bs1r[gi] = sb1[gbase + gi];
        bs2r[gi] = sb2[gbase + gi];
        wi1r[gi] = swi1[gbase + gi];
        int ga = gbase + gi;
        isth[gi] = (ga >= 2*HH && ga < 3*HH);   // 'g' gate chunk -> tanh
    }

    float c1l[4] = {0.f, 0.f, 0.f, 0.f};
    float c2l[4] = {0.f, 0.f, 0.f, 0.f};

    for (int t = 0; t < TT; ++t) {
        const int tc = t & (TCH - 1);
        if (tc == 0) {
            __syncthreads();
            for (int i = tid; i < BT*TCH; i += NT) {
                int b = i / TCH, u = i % TCH;
                xs[i] = x[(size_t)(b0 + b) * TT + t + u];
            }
            __syncthreads();
        }

        // ---------------- Phase A: cell-1 gates (x-term + h1 @ W_hh1^T) --------
        float acc[4][4];
#pragma unroll
        for (int bi = 0; bi < 4; ++bi) {
            float xv = xs[(bbase + bi) * TCH + tc];
#pragma unroll
            for (int gi = 0; gi < 4; ++gi)
                acc[gi][bi] = bs1r[gi] + wi1r[gi] * xv;
        }
#pragma unroll 3
        for (int k = 0; k < HH; ++k) {
            float4 wv = *(const float4*)&sWh1[k*GP + gbase];
            float4 hv = *(const float4*)&h1s[k*BT + bbase];
            float wa[4] = {wv.x, wv.y, wv.z, wv.w};
            float ha[4] = {hv.x, hv.y, hv.z, hv.w};
#pragma unroll
            for (int gi = 0; gi < 4; ++gi)
#pragma unroll
                for (int bi = 0; bi < 4; ++bi)
                    acc[gi][bi] += wa[gi] * ha[bi];
        }
#pragma unroll
        for (int gi = 0; gi < 4; ++gi) {
            float4 sv;
            if (isth[gi])
                sv = make_float4(tanhf(acc[gi][0]), tanhf(acc[gi][1]),
                                 tanhf(acc[gi][2]), tanhf(acc[gi][3]));
            else
                sv = make_float4(sigm(acc[gi][0]), sigm(acc[gi][1]),
                                 sigm(acc[gi][2]), sigm(acc[gi][3]));
            *(float4*)&ag[(gbase + gi) * BT + bbase] = sv;
        }
        __syncthreads();

        // ---------------- Phase B: cell-1 state update -------------------------
        {
            int it = 0;
            for (int idx = tid; idx < HH*BT; idx += NT, ++it) {
                int b = idx & (BT - 1);
                int j = idx / BT;
                float iv = ag[j*BT + b];
                float fv = ag[(HH + j)*BT + b];
                float gv = ag[(2*HH + j)*BT + b];
                float ov = ag[(3*HH + j)*BT + b];
                float c = fv * c1l[it] + iv * gv;
                c1l[it] = c;
                h1s[j*BT + b] = ov * tanhf(c);
            }
        }
        __syncthreads();

        // ---------------- Phase C: cell-2 gates (h1 @ W_ih2^T + h2 @ W_hh2^T) --
#pragma unroll
        for (int gi = 0; gi < 4; ++gi)
#pragma unroll
            for (int bi = 0; bi < 4; ++bi)
                acc[gi][bi] = bs2r[gi];
#pragma unroll 2
        for (int k = 0; k < HH; ++k) {
            float4 w1 = *(const float4*)&sWi2[k*GP + gbase];
            float4 h1v = *(const float4*)&h1s[k*BT + bbase];
            float4 w2 = *(const float4*)&sWh2[k*GP + gbase];
            float4 h2v = *(const float4*)&h2s[k*BT + bbase];
            float wa1[4] = {w1.x, w1.y, w1.z, w1.w};
            float ha1[4] = {h1v.x, h1v.y, h1v.z, h1v.w};
            float wa2[4] = {w2.x, w2.y, w2.z, w2.w};
            float ha2[4] = {h2v.x, h2v.y, h2v.z, h2v.w};
#pragma unroll
            for (int gi = 0; gi < 4; ++gi)
#pragma unroll
                for (int bi = 0; bi < 4; ++bi) {
                    acc[gi][bi] += wa1[gi] * ha1[bi];
                    acc[gi][bi] += wa2[gi] * ha2[bi];
                }
        }
#pragma unroll
        for (int gi = 0; gi < 4; ++gi) {
            float4 sv;
            if (isth[gi])
                sv = make_float4(tanhf(acc[gi][0]), tanhf(acc[gi][1]),
                                 tanhf(acc[gi][2]), tanhf(acc[gi][3]));
            else
                sv = make_float4(sigm(acc[gi][0]), sigm(acc[gi][1]),
                                 sigm(acc[gi][2]), sigm(acc[gi][3]));
            *(float4*)&ag[(gbase + gi) * BT + bbase] = sv;
        }
        __syncthreads();

        // ---------------- Phase D: cell-2 state update -------------------------
        {
            int it = 0;
            for (int idx = tid; idx < HH*BT; idx += NT, ++it) {
                int b = idx & (BT - 1);
                int j = idx / BT;
                float iv = ag[j*BT + b];
                float fv = ag[(HH + j)*BT + b];
                float gv = ag[(2*HH + j)*BT + b];
                float ov = ag[(3*HH + j)*BT + b];
                float c = fv * c2l[it] + iv * gv;
                c2l[it] = c;
                h2s[j*BT + b] = ov * tanhf(c);
            }
        }
        __syncthreads();

        // ---------------- Phase E: fc head -------------------------------------
        if (tid < BT) {
            float a = fcb;
#pragma unroll 3
            for (int k = 0; k < HH; ++k)
                a += h2s[k*BT + tid] * sfcw[k];
            out[(size_t)(b0 + tid) * TT + t] = a;
        }
        // h2s is only rewritten in Phase D(t+1), which is behind 3 barriers; safe.
    }
}

extern "C" void kernel_launch(void* const* d_in, const int* in_sizes, int n_in,
                              void* d_out, int out_size)
{
    const float* x    = (const float*)d_in[0];
    // d_in[1] = future (always 0 for this problem) — ignored
    const float* Wih1 = (const float*)d_in[2];
    const float* bih1 = (const float*)d_in[3];
    const float* Whh1 = (const float*)d_in[4];
    const float* bhh1 = (const float*)d_in[5];
    const float* Wih2 = (const float*)d_in[6];
    const float* bih2 = (const float*)d_in[7];
    const float* Whh2 = (const float*)d_in[8];
    const float* bhh2 = (const float*)d_in[9];
    const float* fcw  = (const float*)d_in[10];
    const float* fcb  = (const float*)d_in[11];
    float* out = (float*)d_out;

    const size_t smem = SMEM_FLOATS * sizeof(float);   // ~161 KB
    cudaFuncSetAttribute(lstm2_persistent_kernel,
                         cudaFuncAttributeMaxDynamicSharedMemorySize, (int)smem);

    lstm2_persistent_kernel<<<BB / BT, NT, smem>>>(
        x, Wih1, bih1, Whh1, bhh1, Wih2, bih2, Whh2, bhh2, fcw, fcb, out);
}

// round 3
// speedup vs baseline: 1.1247x; 1.1247x over previous
#include <cuda_runtime.h>
#include <cstddef>

#define HH 51     // hidden size
#define GG 204    // 4*H real gates
#define GP 224    // padded gate slots (56 groups of 4)
#define BT 16     // batch rows per block
#define NT 224    // threads per block (56 gate-groups x 4 batch-groups)
#define TT 512    // timesteps
#define BB 2048   // batch
#define TCH 64    // x staging chunk (timesteps)

// floats: 3*HH*GP + 3*GP + 64 | u64: 2*HH*BT | floats: GP*BT + BT*TCH
#define SMEM_FLOATS (3*HH*GP + 3*GP + 64 + 2*HH*BT*2 + GP*BT + BT*TCH)

typedef unsigned long long u64;

__device__ __forceinline__ u64 pack2(float lo, float hi) {
    u64 r; asm("mov.b64 %0, {%1,%2};" : "=l"(r) : "f"(lo), "f"(hi)); return r;
}
__device__ __forceinline__ void unpack2(u64 v, float& lo, float& hi) {
    asm("mov.b64 {%0,%1}, %2;" : "=f"(lo), "=f"(hi) : "l"(v));
}
// d = a*b + c, two packed fp32 lanes (sm_100+ FFMA2 path)
__device__ __forceinline__ u64 fma2(u64 a, u64 b, u64 c) {
    u64 d; asm("fma.rn.f32x2 %0, %1, %2, %3;" : "=l"(d) : "l"(a), "l"(b), "l"(c)); return d;
}

// MUFU-only activations (ex2.approx + rcp.approx): ~1e-6 rel error, fine vs 1e-3 tol
__device__ __forceinline__ float sigm(float v)   { return __fdividef(1.f, 1.f + __expf(-v)); }
__device__ __forceinline__ float tanh_f(float v) { return 1.f - 2.f * __fdividef(1.f, 1.f + __expf(2.f * v)); }

__global__ void __launch_bounds__(NT, 1) lstm2_persistent_kernel(
    const float* __restrict__ x,
    const float* __restrict__ Wih1, const float* __restrict__ bih1,
    const float* __restrict__ Whh1, const float* __restrict__ bhh1,
    const float* __restrict__ Wih2, const float* __restrict__ bih2,
    const float* __restrict__ Whh2, const float* __restrict__ bhh2,
    const float* __restrict__ fcwg, const float* __restrict__ fcbg,
    float* __restrict__ out)
{
    extern __shared__ float sm[];
    float* sWh1 = sm;                  // [HH][GP] transposed: sWh1[k*GP+g] = W_hh1[g][k]
    float* sWi2 = sWh1 + HH*GP;        // [HH][GP]
    float* sWh2 = sWi2 + HH*GP;        // [HH][GP]
    float* sb1  = sWh2 + HH*GP;        // [GP] combined bias cell1
    float* sb2  = sb1 + GP;            // [GP] combined bias cell2
    float* swi1 = sb2 + GP;            // [GP] W_ih1 column
    float* sfcw = swi1 + GP;           // [64]
    u64*   h1d  = (u64*)(sfcw + 64);   // [HH][BT] duplicated (h,h)  (offset 35008 floats: 8B-aligned)
    u64*   h2d  = h1d + HH*BT;         // [HH][BT] duplicated
    float* ag   = (float*)(h2d + HH*BT); // [GP][BT] activated gates scratch
    float* xs   = ag + GP*BT;          // [BT][TCH] x staging

    const int tid = threadIdx.x;
    const int b0  = blockIdx.x * BT;

    // ---- one-time weight prep (transpose into SMEM, pad slots >= 204 with 0) ----
    for (int i = tid; i < HH*GP; i += NT) {
        int k = i / GP, g = i % GP;
        bool real = (g < GG);
        sWh1[i] = real ? Whh1[g*HH + k] : 0.f;
        sWi2[i] = real ? Wih2[g*HH + k] : 0.f;
        sWh2[i] = real ? Whh2[g*HH + k] : 0.f;
    }
    for (int g = tid; g < GP; g += NT) {
        bool real = (g < GG);
        sb1[g]  = real ? (bih1[g] + bhh1[g]) : 0.f;
        sb2[g]  = real ? (bih2[g] + bhh2[g]) : 0.f;
        swi1[g] = real ? Wih1[g] : 0.f;      // W_ih1 is [4H,1]
    }
    for (int k = tid; k < 64; k += NT) sfcw[k] = (k < HH) ? fcwg[k] : 0.f;
    for (int i = tid; i < HH*BT; i += NT) { h1d[i] = 0ull; h2d[i] = 0ull; }
    const float fcb = fcbg[0];

    // thread mapping: 56 gate-groups (4 gates = 2 packed pairs) x 4 batch-groups (4 each)
    const int gg_ = tid % 56;
    const int bq  = tid / 56;
    const int gbase = gg_ * 4;
    const int bbase = bq * 4;

    __syncthreads();

    // per-thread packed constants: gate pairs (g0,g1),(g2,g3)
    u64 b1p[2], b2p[2], wi1p[2];
    b1p[0]  = *(const u64*)&sb1[gbase];     b1p[1]  = *(const u64*)&sb1[gbase + 2];
    b2p[0]  = *(const u64*)&sb2[gbase];     b2p[1]  = *(const u64*)&sb2[gbase + 2];
    wi1p[0] = *(const u64*)&swi1[gbase];    wi1p[1] = *(const u64*)&swi1[gbase + 2];

    bool isth[4];
#pragma unroll
    for (int gi = 0; gi < 4; ++gi) {
        int ga = gbase + gi;
        isth[gi] = (ga >= 2*HH && ga < 3*HH);   // 'g' gate chunk -> tanh
    }

    float c1l[4] = {0.f, 0.f, 0.f, 0.f};
    float c2l[4] = {0.f, 0.f, 0.f, 0.f};

    for (int t = 0; t < TT; ++t) {
        const int tc = t & (TCH - 1);
        if (tc == 0) {
            __syncthreads();
            for (int i = tid; i < BT*TCH; i += NT) {
                int b = i / TCH, u = i % TCH;
                xs[i] = x[(size_t)(b0 + b) * TT + t + u];
            }
            __syncthreads();
        }

        // ---------------- Phase A: cell-1 gates (x-term + h1 @ W_hh1^T) --------
        u64 acc[2][4];
#pragma unroll
        for (int bi = 0; bi < 4; ++bi) {
            float xv = xs[(bbase + bi) * TCH + tc];
            u64 xd = pack2(xv, xv);
            acc[0][bi] = fma2(wi1p[0], xd, b1p[0]);
            acc[1][bi] = fma2(wi1p[1], xd, b1p[1]);
        }
#pragma unroll 3
        for (int k = 0; k < HH; ++k) {
            ulonglong2 wv = *(const ulonglong2*)&sWh1[k*GP + gbase];   // (w0,w1),(w2,w3)
            ulonglong2 hv0 = *(const ulonglong2*)&h1d[k*BT + bbase];   // (h0,h0),(h1,h1)
            ulonglong2 hv1 = *(const ulonglong2*)&h1d[k*BT + bbase + 2];
            acc[0][0] = fma2(wv.x, hv0.x, acc[0][0]);
            acc[1][0] = fma2(wv.y, hv0.x, acc[1][0]);
            acc[0][1] = fma2(wv.x, hv0.y, acc[0][1]);
            acc[1][1] = fma2(wv.y, hv0.y, acc[1][1]);
            acc[0][2] = fma2(wv.x, hv1.x, acc[0][2]);
            acc[1][2] = fma2(wv.y, hv1.x, acc[1][2]);
            acc[0][3] = fma2(wv.x, hv1.y, acc[0][3]);
            acc[1][3] = fma2(wv.y, hv1.y, acc[1][3]);
        }
        {
            float a[4][4];
#pragma unroll
            for (int bi = 0; bi < 4; ++bi) {
                unpack2(acc[0][bi], a[0][bi], a[1][bi]);
                unpack2(acc[1][bi], a[2][bi], a[3][bi]);
            }
#pragma unroll
            for (int gi = 0; gi < 4; ++gi) {
                float4 sv;
                if (isth[gi])
                    sv = make_float4(tanh_f(a[gi][0]), tanh_f(a[gi][1]),
                                     tanh_f(a[gi][2]), tanh_f(a[gi][3]));
                else
                    sv = make_float4(sigm(a[gi][0]), sigm(a[gi][1]),
                                     sigm(a[gi][2]), sigm(a[gi][3]));
                *(float4*)&ag[(gbase + gi) * BT + bbase] = sv;
            }
        }
        __syncthreads();

        // ---------------- Phase B: cell-1 state update -------------------------
        {
            int it = 0;
            for (int idx = tid; idx < HH*BT; idx += NT, ++it) {
                int b = idx & (BT - 1);
                int j = idx / BT;
                float iv = ag[j*BT + b];
                float fv = ag[(HH + j)*BT + b];
                float gv = ag[(2*HH + j)*BT + b];
                float ov = ag[(3*HH + j)*BT + b];
                float c = fv * c1l[it] + iv * gv;
                c1l[it] = c;
                float h = ov * tanh_f(c);
                h1d[j*BT + b] = pack2(h, h);
            }
        }
        __syncthreads();

        // ---------------- Phase C: cell-2 gates (h1 @ W_ih2^T + h2 @ W_hh2^T) --
        acc[0][0] = b2p[0]; acc[0][1] = b2p[0]; acc[0][2] = b2p[0]; acc[0][3] = b2p[0];
        acc[1][0] = b2p[1]; acc[1][1] = b2p[1]; acc[1][2] = b2p[1]; acc[1][3] = b2p[1];
#pragma unroll 2
        for (int k = 0; k < HH; ++k) {
            ulonglong2 w1v = *(const ulonglong2*)&sWi2[k*GP + gbase];
            ulonglong2 w2v = *(const ulonglong2*)&sWh2[k*GP + gbase];
            ulonglong2 h1v0 = *(const ulonglong2*)&h1d[k*BT + bbase];
            ulonglong2 h1v1 = *(const ulonglong2*)&h1d[k*BT + bbase + 2];
            ulonglong2 h2v0 = *(const ulonglong2*)&h2d[k*BT + bbase];
            ulonglong2 h2v1 = *(const ulonglong2*)&h2d[k*BT + bbase + 2];
            acc[0][0] = fma2(w1v.x, h1v0.x, acc[0][0]);
            acc[1][0] = fma2(w1v.y, h1v0.x, acc[1][0]);
            acc[0][1] = fma2(w1v.x, h1v0.y, acc[0][1]);
            acc[1][1] = fma2(w1v.y, h1v0.y, acc[1][1]);
            acc[0][2] = fma2(w1v.x, h1v1.x, acc[0][2]);
            acc[1][2] = fma2(w1v.y, h1v1.x, acc[1][2]);
            acc[0][3] = fma2(w1v.x, h1v1.y, acc[0][3]);
            acc[1][3] = fma2(w1v.y, h1v1.y, acc[1][3]);
            acc[0][0] = fma2(w2v.x, h2v0.x, acc[0][0]);
            acc[1][0] = fma2(w2v.y, h2v0.x, acc[1][0]);
            acc[0][1] = fma2(w2v.x, h2v0.y, acc[0][1]);
            acc[1][1] = fma2(w2v.y, h2v0.y, acc[1][1]);
            acc[0][2] = fma2(w2v.x, h2v1.x, acc[0][2]);
            acc[1][2] = fma2(w2v.y, h2v1.x, acc[1][2]);
            acc[0][3] = fma2(w2v.x, h2v1.y, acc[0][3]);
            acc[1][3] = fma2(w2v.y, h2v1.y, acc[1][3]);
        }
        {
            float a[4][4];
#pragma unroll
            for (int bi = 0; bi < 4; ++bi) {
                unpack2(acc[0][bi], a[0][bi], a[1][bi]);
                unpack2(acc[1][bi], a[2][bi], a[3][bi]);
            }
#pragma unroll
            for (int gi = 0; gi < 4; ++gi) {
                float4 sv;
                if (isth[gi])
                    sv = make_float4(tanh_f(a[gi][0]), tanh_f(a[gi][1]),
                                     tanh_f(a[gi][2]), tanh_f(a[gi][3]));
                else
                    sv = make_float4(sigm(a[gi][0]), sigm(a[gi][1]),
                                     sigm(a[gi][2]), sigm(a[gi][3]));
                *(float4*)&ag[(gbase + gi) * BT + bbase] = sv;
            }
        }
        __syncthreads();

        // ---------------- Phase D: cell-2 state update -------------------------
        {
            int it = 0;
            for (int idx = tid; idx < HH*BT; idx += NT, ++it) {
                int b = idx & (BT - 1);
                int j = idx / BT;
                float iv = ag[j*BT + b];
                float fv = ag[(HH + j)*BT + b];
                float gv = ag[(2*HH + j)*BT + b];
                float ov = ag[(3*HH + j)*BT + b];
                float c = fv * c2l[it] + iv * gv;
                c2l[it] = c;
                float h = ov * tanh_f(c);
                h2d[j*BT + b] = pack2(h, h);
            }
        }
        __syncthreads();

        // ---------------- Phase E: fc head -------------------------------------
        if (tid < BT) {
            float a = fcb;
#pragma unroll 3
            for (int k = 0; k < HH; ++k)
                a += (*(const float*)&h2d[k*BT + tid]) * sfcw[k];   // low half of (h,h)
            out[(size_t)(b0 + tid) * TT + t] = a;
        }
        // h2d is only rewritten in Phase D(t+1), which is behind 3 barriers; safe.
    }
}

extern "C" void kernel_launch(void* const* d_in, const int* in_sizes, int n_in,
                              void* d_out, int out_size)
{
    const float* x    = (const float*)d_in[0];
    // d_in[1] = future (always 0 for this problem) — ignored
    const float* Wih1 = (const float*)d_in[2];
    const float* bih1 = (const float*)d_in[3];
    const float* Whh1 = (const float*)d_in[4];
    const float* bhh1 = (const float*)d_in[5];
    const float* Wih2 = (const float*)d_in[6];
    const float* bih2 = (const float*)d_in[7];
    const float* Whh2 = (const float*)d_in[8];
    const float* bhh2 = (const float*)d_in[9];
    const float* fcw  = (const float*)d_in[10];
    const float* fcb  = (const float*)d_in[11];
    float* out = (float*)d_out;

    const size_t smem = SMEM_FLOATS * sizeof(float);   // ~171.5 KB
    cudaFuncSetAttribute(lstm2_persistent_kernel,
                         cudaFuncAttributeMaxDynamicSharedMemorySize, (int)smem);

    lstm2_persistent_kernel<<<BB / BT, NT, smem>>>(
        x, Wih1, bih1, Whh1, bhh1, Wih2, bih2, Whh2, bhh2, fcw, fcb, out);
}